// round 4
// baseline (speedup 1.0000x reference)
#include <cuda_runtime.h>
#include <mma.h>
#include <cstdint>
#include <cstddef>

using namespace nvcuda;

// Problem dims
#define BB   64
#define TT   512
#define DD   512
#define HH   1024
#define OO   512
#define LL   2
#define G3   (3 * HH)          // 3072
#define BT   (BB * TT)         // 32768

#define NBLK 128               // persistent blocks (64 per direction)

// ---------------------------------------------------------------------------
// Scratch (static device memory; allocation-free per harness rules)
// ---------------------------------------------------------------------------
__device__ float g_gx[2][(size_t)BT * G3];       // per-dir input gates [BT, 3H]
__device__ float g_y0[2][(size_t)BT * HH];       // layer-0 outputs per dir
__device__ float g_y1[2][(size_t)BT * HH];       // layer-1 outputs per dir
__device__ float g_h[2][2][BB * HH];             // compact h, [dir][parity][64][1024]
__device__ unsigned g_bar_count;
__device__ unsigned g_bar_epoch;

__global__ void reset_bar()
{
    g_bar_count = 0;
    g_bar_epoch = 0;
}

// ---------------------------------------------------------------------------
// Generic TF32 WMMA GEMM: C[M,N] (+)= A[M,K] @ B[K,N]
// 128x128 tile per block, BK=16, 256 threads.
// ---------------------------------------------------------------------------
__global__ void __launch_bounds__(256, 2)
gemm_tf32(const float* __restrict__ A, const float* __restrict__ Bg,
          float* __restrict__ C, int M, int N, int K, int accumulate)
{
    __shared__ float As[16][132];   // As[k][m]  (A transposed into smem)
    __shared__ float Bs[16][132];   // Bs[k][n]

    const int bm   = blockIdx.y * 128;
    const int bn   = blockIdx.x * 128;
    const int tid  = threadIdx.x;
    const int warp = tid >> 5;
    const int wm   = (warp & 3) * 32;
    const int wn   = (warp >> 2) * 64;

    wmma::fragment<wmma::accumulator, 16, 16, 8, float> acc[2][4];
#pragma unroll
    for (int i = 0; i < 2; i++)
#pragma unroll
        for (int j = 0; j < 4; j++)
            wmma::fill_fragment(acc[i][j], 0.0f);

    const int lm  = tid & 127;
    const int lkh = (tid >> 7) * 8;

    for (int k0 = 0; k0 < K; k0 += 16) {
        const float* ap = A + (size_t)(bm + lm) * K + k0 + lkh;
        float4 a0 = *(const float4*)(ap);
        float4 a1 = *(const float4*)(ap + 4);
        As[lkh + 0][lm] = a0.x; As[lkh + 1][lm] = a0.y;
        As[lkh + 2][lm] = a0.z; As[lkh + 3][lm] = a0.w;
        As[lkh + 4][lm] = a1.x; As[lkh + 5][lm] = a1.y;
        As[lkh + 6][lm] = a1.z; As[lkh + 7][lm] = a1.w;
#pragma unroll
        for (int i = 0; i < 2; i++) {
            int q  = tid + i * 256;
            int kk = q >> 5;
            int n4 = (q & 31) * 4;
            *(float4*)&Bs[kk][n4] =
                *(const float4*)(Bg + (size_t)(k0 + kk) * N + bn + n4);
        }
        __syncthreads();

#pragma unroll
        for (int kk = 0; kk < 16; kk += 8) {
            wmma::fragment<wmma::matrix_a, 16, 16, 8, wmma::precision::tf32,
                           wmma::col_major> af[2];
#pragma unroll
            for (int i = 0; i < 2; i++) {
                wmma::load_matrix_sync(af[i], &As[kk][wm + i * 16], 132);
#pragma unroll
                for (int e = 0; e < af[i].num_elements; e++)
                    af[i].x[e] = wmma::__float_to_tf32(af[i].x[e]);
            }
#pragma unroll
            for (int j = 0; j < 4; j++) {
                wmma::fragment<wmma::matrix_b, 16, 16, 8, wmma::precision::tf32,
                               wmma::row_major> bf;
                wmma::load_matrix_sync(bf, &Bs[kk][wn + j * 16], 132);
#pragma unroll
                for (int e = 0; e < bf.num_elements; e++)
                    bf.x[e] = wmma::__float_to_tf32(bf.x[e]);
#pragma unroll
                for (int i = 0; i < 2; i++)
                    wmma::mma_sync(acc[i][j], af[i], bf, acc[i][j]);
            }
        }
        __syncthreads();
    }

#pragma unroll
    for (int i = 0; i < 2; i++)
#pragma unroll
        for (int j = 0; j < 4; j++) {
            float* cp = C + (size_t)(bm + wm + i * 16) * N + bn + wn + j * 16;
            if (accumulate) {
                wmma::fragment<wmma::accumulator, 16, 16, 8, float> cf;
                wmma::load_matrix_sync(cf, cp, N, wmma::mem_row_major);
#pragma unroll
                for (int e = 0; e < cf.num_elements; e++)
                    acc[i][j].x[e] += cf.x[e];
            }
            wmma::store_matrix_sync(cp, acc[i][j], N, wmma::mem_row_major);
        }
}

// ---------------------------------------------------------------------------
// Persistent GRU layer kernel: 128 blocks (64 per dir), each owns 16 h-cols.
// Wh slice (1024 x 48, tf32-rounded) resident in SMEM for all 512 steps.
// Per step: gh[64,48] = h_prev[64,1024] @ Whs via TF32 WMMA (warps split
// m2 x k2), then pointwise GRU update; grid barrier between steps.
// ---------------------------------------------------------------------------
#define WHS_F   (HH * 48)            // 49152 floats
#define AS_F    (2 * 16 * 68)        // 2176 floats (ki half, k, m)
#define GS_F    (64 * 48)            // 3072 floats
#define SMEM_F  (WHS_F + AS_F + GS_F)
#define SMEM_BYTES (SMEM_F * 4)      // 217600 bytes

__device__ __forceinline__ void grid_barrier(unsigned e)
{
    __syncthreads();
    if (threadIdx.x == 0) {
        __threadfence();
        unsigned arr = atomicAdd(&g_bar_count, 1u);
        if (arr == e * NBLK - 1u) {
            atomicExch(&g_bar_epoch, e);
        } else {
            while (*(volatile unsigned*)&g_bar_epoch < e) __nanosleep(32);
        }
        __threadfence();
    }
    __syncthreads();
}

__global__ void __launch_bounds__(128, 1)
gru_layer(const float* __restrict__ Wh_fw, const float* __restrict__ Wh_bw,
          const float* __restrict__ bx_fw, const float* __restrict__ bh_fw,
          const float* __restrict__ bx_bw, const float* __restrict__ bh_bw,
          float* __restrict__ y_fw, float* __restrict__ y_bw)
{
    extern __shared__ float smem[];
    float* Whs = smem;                 // [1024][48]
    float* As  = smem + WHS_F;         // [2][16][68]
    float* Gs  = smem + WHS_F + AS_F;  // [64][48]

    const int bid = blockIdx.x;
    const int dir = bid >> 6;          // 0 = fw, 1 = bw
    const int c0  = (bid & 63) * 16;   // h-column base

    const float* Wh = dir ? Wh_bw : Wh_fw;
    const float* bx = dir ? bx_bw : bx_fw;
    const float* bh = dir ? bh_bw : bh_fw;
    float*       y  = dir ? y_bw  : y_fw;
    const float* gx = g_gx[dir];

    const int tid  = threadIdx.x;
    const int warp = tid >> 5;
    const int mi   = warp & 1;         // m half (rows mi*32 .. +32)
    const int ki   = warp >> 1;        // k half (k ki*512 .. +512)

    // ---- stage Wh slice into SMEM, tf32-rounded (once) ----
    for (int i = tid; i < WHS_F; i += 128) {
        int k = i / 48;
        int col = i - k * 48;
        int g = col >> 4;
        int j = col & 15;
        Whs[i] = wmma::__float_to_tf32(Wh[(size_t)k * G3 + g * HH + c0 + j]);
    }
    __syncthreads();

    // staging map: half = tid>>6 selects which ki-half chunk, m = tid&63
    const int st_half = tid >> 6;
    const int st_m    = tid & 63;

    for (int s = 0; s < TT; s++) {
        const int t  = dir ? (TT - 1 - s) : s;
        const float* hread  = g_h[dir][(s + 1) & 1];  // h_{s-1}
        float*       hwrite = g_h[dir][s & 1];        // h_s

        wmma::fragment<wmma::accumulator, 16, 16, 8, float> acc[2][3];
#pragma unroll
        for (int f = 0; f < 2; f++)
#pragma unroll
            for (int n = 0; n < 3; n++)
                wmma::fill_fragment(acc[f][n], 0.0f);

        if (s > 0) {
            // prologue: stage chunk 0 (both k-halves)
            {
                const float* src = hread + st_m * HH + st_half * 512;
                float4 r0 = __ldcg((const float4*)(src));
                float4 r1 = __ldcg((const float4*)(src + 4));
                float4 r2 = __ldcg((const float4*)(src + 8));
                float4 r3 = __ldcg((const float4*)(src + 12));
                float* d = As + st_half * (16 * 68) + st_m;
                d[0*68]=r0.x; d[1*68]=r0.y; d[2*68]=r0.z;  d[3*68]=r0.w;
                d[4*68]=r1.x; d[5*68]=r1.y; d[6*68]=r1.z;  d[7*68]=r1.w;
                d[8*68]=r2.x; d[9*68]=r2.y; d[10*68]=r2.z; d[11*68]=r2.w;
                d[12*68]=r3.x;d[13*68]=r3.y;d[14*68]=r3.z; d[15*68]=r3.w;
            }
            for (int c = 0; c < 32; c++) {
                __syncthreads();   // staged chunk c visible
                // prefetch chunk c+1 into registers
                float4 p0, p1, p2, p3;
                if (c < 31) {
                    const float* src = hread + st_m * HH + st_half * 512 + (c + 1) * 16;
                    p0 = __ldcg((const float4*)(src));
                    p1 = __ldcg((const float4*)(src + 4));
                    p2 = __ldcg((const float4*)(src + 8));
                    p3 = __ldcg((const float4*)(src + 12));
                }
                // mma on chunk c (this warp's k-half)
                const int kb = ki * 512 + c * 16;
                const float* AsH = As + ki * (16 * 68);
#pragma unroll
                for (int kk = 0; kk < 16; kk += 8) {
                    wmma::fragment<wmma::matrix_a, 16, 16, 8,
                                   wmma::precision::tf32, wmma::col_major> af[2];
#pragma unroll
                    for (int f = 0; f < 2; f++)
                        wmma::load_matrix_sync(af[f],
                            AsH + kk * 68 + mi * 32 + f * 16, 68);
#pragma unroll
                    for (int n = 0; n < 3; n++) {
                        wmma::fragment<wmma::matrix_b, 16, 16, 8,
                                       wmma::precision::tf32, wmma::row_major> bf;
                        wmma::load_matrix_sync(bf, Whs + (kb + kk) * 48 + n * 16, 48);
#pragma unroll
                        for (int f = 0; f < 2; f++)
                            wmma::mma_sync(acc[f][n], af[f], bf, acc[f][n]);
                    }
                }
                __syncthreads();   // done reading As chunk c
                if (c < 31) {
                    float* d = As + st_half * (16 * 68) + st_m;
                    d[0*68]=p0.x; d[1*68]=p0.y; d[2*68]=p0.z;  d[3*68]=p0.w;
                    d[4*68]=p1.x; d[5*68]=p1.y; d[6*68]=p1.z;  d[7*68]=p1.w;
                    d[8*68]=p2.x; d[9*68]=p2.y; d[10*68]=p2.z; d[11*68]=p2.w;
                    d[12*68]=p3.x;d[13*68]=p3.y;d[14*68]=p3.z; d[15*68]=p3.w;
                }
            }
        }

        // ---- cross-warp k-reduction into Gs ----
        if (ki == 1) {
#pragma unroll
            for (int f = 0; f < 2; f++)
#pragma unroll
                for (int n = 0; n < 3; n++)
                    wmma::store_matrix_sync(Gs + (mi * 32 + f * 16) * 48 + n * 16,
                                            acc[f][n], 48, wmma::mem_row_major);
        }
        __syncthreads();
        if (ki == 0) {
#pragma unroll
            for (int f = 0; f < 2; f++)
#pragma unroll
                for (int n = 0; n < 3; n++) {
                    wmma::fragment<wmma::accumulator, 16, 16, 8, float> cf;
                    wmma::load_matrix_sync(cf,
                        Gs + (mi * 32 + f * 16) * 48 + n * 16, 48,
                        wmma::mem_row_major);
#pragma unroll
                    for (int e = 0; e < cf.num_elements; e++)
                        acc[f][n].x[e] += cf.x[e];
                    wmma::store_matrix_sync(Gs + (mi * 32 + f * 16) * 48 + n * 16,
                                            acc[f][n], 48, wmma::mem_row_major);
                }
        }
        __syncthreads();

        // ---- pointwise GRU update: 64 rows x 16 cols ----
#pragma unroll
        for (int r = 0; r < 8; r++) {
            int idx = tid + r * 128;
            int m = idx >> 4;
            int j = idx & 15;
            int hc = c0 + j;
            float ghr = Gs[m * 48 + j]      + bh[hc];
            float ghz = Gs[m * 48 + 16 + j] + bh[HH + hc];
            float ghn = Gs[m * 48 + 32 + j] + bh[2 * HH + hc];
            size_t gb = ((size_t)m * TT + t) * (size_t)G3;
            float xr = gx[gb + hc]          + bx[hc];
            float xz = gx[gb + HH + hc]     + bx[HH + hc];
            float xn = gx[gb + 2 * HH + hc] + bx[2 * HH + hc];
            float rg = 1.f / (1.f + __expf(-(xr + ghr)));
            float zg = 1.f / (1.f + __expf(-(xz + ghz)));
            float ng = tanhf(xn + rg * ghn);
            float hp = (s > 0) ? __ldcg(&hread[m * HH + hc]) : 0.f;
            float h  = (1.f - zg) * ng + zg * hp;
            y[((size_t)m * TT + t) * HH + hc] = h;
            __stcg(&hwrite[m * HH + hc], wmma::__float_to_tf32(h));
        }

        grid_barrier((unsigned)(s + 1));
    }
}

// ---------------------------------------------------------------------------
// FC bias prefill + final-hidden extraction
// ---------------------------------------------------------------------------
__global__ void fill_bias(float* __restrict__ out, const float* __restrict__ b)
{
    size_t i = (size_t)blockIdx.x * blockDim.x + threadIdx.x;
    if (i < (size_t)BT * OO) out[i] = b[i & (OO - 1)];
}

__global__ void write_finals(float* __restrict__ out)
{
    int i = blockIdx.x * blockDim.x + threadIdx.x;  // 0 .. 2*L*B*H-1
    int j = i & (HH - 1);
    int b = (i >> 10) & (BB - 1);
    int l = (i >> 16) & 1;
    int d = i >> 17;                                 // 0 = fw_h, 1 = bw_h
    const float* y = (l == 0) ? g_y0[d] : g_y1[d];
    int t = d ? 0 : (TT - 1);
    out[(size_t)BT * OO + i] = y[((size_t)b * TT + t) * HH + j];
}

// ---------------------------------------------------------------------------
// Launch sequence (graph-capturable: ~12 kernel launches, no allocs)
// ---------------------------------------------------------------------------
extern "C" void kernel_launch(void* const* d_in, const int* in_sizes, int n_in,
                              void* d_out, int out_size)
{
    const float* x       = (const float*)d_in[0];
    const float* fw_Wx0  = (const float*)d_in[1];
    const float* fw_Wh0  = (const float*)d_in[2];
    const float* fw_bx0  = (const float*)d_in[3];
    const float* fw_bh0  = (const float*)d_in[4];
    const float* fw_Wx1  = (const float*)d_in[5];
    const float* fw_Wh1  = (const float*)d_in[6];
    const float* fw_bx1  = (const float*)d_in[7];
    const float* fw_bh1  = (const float*)d_in[8];
    const float* bw_Wx0  = (const float*)d_in[9];
    const float* bw_Wh0  = (const float*)d_in[10];
    const float* bw_bx0  = (const float*)d_in[11];
    const float* bw_bh0  = (const float*)d_in[12];
    const float* bw_Wx1  = (const float*)d_in[13];
    const float* bw_Wh1  = (const float*)d_in[14];
    const float* bw_bx1  = (const float*)d_in[15];
    const float* bw_bh1  = (const float*)d_in[16];
    const float* fc_W    = (const float*)d_in[17];
    const float* fc_b    = (const float*)d_in[18];
    float* out = (float*)d_out;

    cudaFuncSetAttribute(gru_layer, cudaFuncAttributeMaxDynamicSharedMemorySize,
                         SMEM_BYTES);

    void* p;
    cudaGetSymbolAddress(&p, g_gx);
    float* gx0 = (float*)p;
    float* gx1 = gx0 + (size_t)BT * G3;
    cudaGetSymbolAddress(&p, g_y0);
    float* y00 = (float*)p;
    float* y01 = y00 + (size_t)BT * HH;
    cudaGetSymbolAddress(&p, g_y1);
    float* y10 = (float*)p;
    float* y11 = y10 + (size_t)BT * HH;

    dim3 ggx(G3 / 128, BT / 128);   // (24, 256)
    dim3 gfc(OO / 128, BT / 128);   // (4, 256)

    // Layer 0 input gates
    gemm_tf32<<<ggx, 256>>>(x, fw_Wx0, gx0, BT, G3, DD, 0);
    gemm_tf32<<<ggx, 256>>>(x, bw_Wx0, gx1, BT, G3, DD, 0);

    // Layer 0 recurrence (persistent, both dirs)
    reset_bar<<<1, 1>>>();
    gru_layer<<<NBLK, 128, SMEM_BYTES>>>(fw_Wh0, bw_Wh0, fw_bx0, fw_bh0,
                                         bw_bx0, bw_bh0, y00, y01);

    // Layer 1 input gates
    gemm_tf32<<<ggx, 256>>>(y00, fw_Wx1, gx0, BT, G3, HH, 0);
    gemm_tf32<<<ggx, 256>>>(y01, bw_Wx1, gx1, BT, G3, HH, 0);

    // Layer 1 recurrence
    reset_bar<<<1, 1>>>();
    gru_layer<<<NBLK, 128, SMEM_BYTES>>>(fw_Wh1, bw_Wh1, fw_bx1, fw_bh1,
                                         bw_bx1, bw_bh1, y10, y11);

    // FC: out = [fw_y1, bw_y1] @ fc_W + fc_b  (split-K over the two halves)
    fill_bias<<<((size_t)BT * OO + 255) / 256, 256>>>(out, fc_b);
    gemm_tf32<<<gfc, 256>>>(y10, fc_W,                   out, BT, OO, HH, 1);
    gemm_tf32<<<gfc, 256>>>(y11, fc_W + (size_t)HH * OO, out, BT, OO, HH, 1);

    // Final hidden states: fw_h [L,B,H] then bw_h [L,B,H]
    write_finals<<<(2 * LL * BB * HH) / 256, 256>>>(out);
}

// round 5
// speedup vs baseline: 1.1445x; 1.1445x over previous
#include <cuda_runtime.h>
#include <mma.h>
#include <cstdint>
#include <cstddef>

using namespace nvcuda;

// Problem dims
#define BB   64
#define TT   512
#define DD   512
#define HH   1024
#define OO   512
#define LL   2
#define G3   (3 * HH)          // 3072
#define BT   (BB * TT)         // 32768

#define NBLK 128               // persistent blocks (64 per direction)

// ---------------------------------------------------------------------------
// Scratch (static device memory; allocation-free per harness rules)
// ---------------------------------------------------------------------------
__device__ float g_gx[2][(size_t)BT * G3];       // per-dir input gates [BT, 3H]
__device__ float g_y0[2][(size_t)BT * HH];       // layer-0 outputs per dir
__device__ float g_y1[2][(size_t)BT * HH];       // layer-1 outputs per dir
__device__ float g_h[2][2][BB * HH];             // compact h, [dir][parity][64][1024]
__device__ unsigned g_bar_count;
__device__ unsigned g_bar_epoch;

__global__ void reset_bar()
{
    g_bar_count = 0;
    g_bar_epoch = 0;
}

// ---------------------------------------------------------------------------
// Generic TF32 WMMA GEMM: C[M,N] (+)= A[M,K] @ B[K,N]  (unchanged from R3)
// ---------------------------------------------------------------------------
__global__ void __launch_bounds__(256, 2)
gemm_tf32(const float* __restrict__ A, const float* __restrict__ Bg,
          float* __restrict__ C, int M, int N, int K, int accumulate)
{
    __shared__ float As[16][132];
    __shared__ float Bs[16][132];

    const int bm   = blockIdx.y * 128;
    const int bn   = blockIdx.x * 128;
    const int tid  = threadIdx.x;
    const int warp = tid >> 5;
    const int wm   = (warp & 3) * 32;
    const int wn   = (warp >> 2) * 64;

    wmma::fragment<wmma::accumulator, 16, 16, 8, float> acc[2][4];
#pragma unroll
    for (int i = 0; i < 2; i++)
#pragma unroll
        for (int j = 0; j < 4; j++)
            wmma::fill_fragment(acc[i][j], 0.0f);

    const int lm  = tid & 127;
    const int lkh = (tid >> 7) * 8;

    for (int k0 = 0; k0 < K; k0 += 16) {
        const float* ap = A + (size_t)(bm + lm) * K + k0 + lkh;
        float4 a0 = *(const float4*)(ap);
        float4 a1 = *(const float4*)(ap + 4);
        As[lkh + 0][lm] = a0.x; As[lkh + 1][lm] = a0.y;
        As[lkh + 2][lm] = a0.z; As[lkh + 3][lm] = a0.w;
        As[lkh + 4][lm] = a1.x; As[lkh + 5][lm] = a1.y;
        As[lkh + 6][lm] = a1.z; As[lkh + 7][lm] = a1.w;
#pragma unroll
        for (int i = 0; i < 2; i++) {
            int q  = tid + i * 256;
            int kk = q >> 5;
            int n4 = (q & 31) * 4;
            *(float4*)&Bs[kk][n4] =
                *(const float4*)(Bg + (size_t)(k0 + kk) * N + bn + n4);
        }
        __syncthreads();

#pragma unroll
        for (int kk = 0; kk < 16; kk += 8) {
            wmma::fragment<wmma::matrix_a, 16, 16, 8, wmma::precision::tf32,
                           wmma::col_major> af[2];
#pragma unroll
            for (int i = 0; i < 2; i++) {
                wmma::load_matrix_sync(af[i], &As[kk][wm + i * 16], 132);
#pragma unroll
                for (int e = 0; e < af[i].num_elements; e++)
                    af[i].x[e] = wmma::__float_to_tf32(af[i].x[e]);
            }
#pragma unroll
            for (int j = 0; j < 4; j++) {
                wmma::fragment<wmma::matrix_b, 16, 16, 8, wmma::precision::tf32,
                               wmma::row_major> bf;
                wmma::load_matrix_sync(bf, &Bs[kk][wn + j * 16], 132);
#pragma unroll
                for (int e = 0; e < bf.num_elements; e++)
                    bf.x[e] = wmma::__float_to_tf32(bf.x[e]);
#pragma unroll
                for (int i = 0; i < 2; i++)
                    wmma::mma_sync(acc[i][j], af[i], bf, acc[i][j]);
            }
        }
        __syncthreads();
    }

#pragma unroll
    for (int i = 0; i < 2; i++)
#pragma unroll
        for (int j = 0; j < 4; j++) {
            float* cp = C + (size_t)(bm + wm + i * 16) * N + bn + wn + j * 16;
            if (accumulate) {
                wmma::fragment<wmma::accumulator, 16, 16, 8, float> cf;
                wmma::load_matrix_sync(cf, cp, N, wmma::mem_row_major);
#pragma unroll
                for (int e = 0; e < cf.num_elements; e++)
                    acc[i][j].x[e] += cf.x[e];
            }
            wmma::store_matrix_sync(cp, acc[i][j], N, wmma::mem_row_major);
        }
}

// ---------------------------------------------------------------------------
// Persistent GRU layer kernel v2.
// 128 blocks (64/dir), 256 threads (8 warps = k4 x m2), 1 block/SM.
// Wh slice [1024,48] tf32-rounded resident in SMEM. Per step each warp
// computes a 32m x 48n x 256k partial with a distance-3 LDG prefetch pipeline
// through a private double-buffered smem staging area; 4-way k-reduction in
// smem; pointwise GRU with gx/h_prev prefetched at step start.
// ---------------------------------------------------------------------------
#define WHS_F   (HH * 48)            // 49152 floats (196608 B)
#define OVL_F   6144                 // overlay: max(8*576 staging, 4*1536 red)
#define SMEM_BYTES ((WHS_F + OVL_F) * 4)   // 221184 B

__device__ __forceinline__ void grid_barrier(unsigned e)
{
    __syncthreads();
    if (threadIdx.x == 0) {
        __threadfence();
        unsigned arr = atomicAdd(&g_bar_count, 1u);
        if (arr == e * NBLK - 1u) {
            atomicExch(&g_bar_epoch, e);
        } else {
            while (*(volatile unsigned*)&g_bar_epoch < e) __nanosleep(32);
        }
        __threadfence();
    }
    __syncthreads();
}

__global__ void __launch_bounds__(256, 1)
gru_layer(const float* __restrict__ Wh_fw, const float* __restrict__ Wh_bw,
          const float* __restrict__ bx_fw, const float* __restrict__ bh_fw,
          const float* __restrict__ bx_bw, const float* __restrict__ bh_bw,
          float* __restrict__ y_fw, float* __restrict__ y_bw)
{
    extern __shared__ float smem[];
    float* Whs = smem;             // [1024][48] tf32
    float* XB  = smem + WHS_F;     // overlay: staging buffers / reduction

    const int bid = blockIdx.x;
    const int dir = bid >> 6;          // 0 = fw, 1 = bw
    const int c0  = (bid & 63) * 16;   // h-column base

    const float* Wh = dir ? Wh_bw : Wh_fw;
    const float* bx = dir ? bx_bw : bx_fw;
    const float* bh = dir ? bh_bw : bh_fw;
    float*       y  = dir ? y_bw  : y_fw;
    const float* gx = g_gx[dir];

    const int tid  = threadIdx.x;
    const int warp = tid >> 5;
    const int lane = tid & 31;
    const int ki   = warp >> 1;        // k quarter (256)
    const int mi   = warp & 1;         // m half (32 rows)

    float* mybuf = XB + warp * 576;    // 2 x [8k][36] private staging

    // ---- stage Wh slice into SMEM, tf32-rounded (once) ----
    for (int i = tid; i < WHS_F; i += 256) {
        int k = i / 48;
        int col = i - k * 48;
        int g = col >> 4;
        int j = col & 15;
        Whs[i] = wmma::__float_to_tf32(Wh[(size_t)k * G3 + g * HH + c0 + j]);
    }

    // ---- per-thread pointwise constants ----
    const int pm  = tid >> 2;          // batch row (0..63)
    const int pj  = (tid & 3) * 4;     // 4 consecutive cols
    const int phc = c0 + pj;
    float br[4], bz[4], bxn_[4], bhn_[4];
#pragma unroll
    for (int q = 0; q < 4; q++) {
        int hc = phc + q;
        br[q]   = bx[hc] + bh[hc];
        bz[q]   = bx[HH + hc] + bh[HH + hc];
        bxn_[q] = bx[2 * HH + hc];
        bhn_[q] = bh[2 * HH + hc];
    }
    __syncthreads();

    const int myrow = mi * 32 + lane;  // staged h row for this lane

    for (int s = 0; s < TT; s++) {
        const int t = dir ? (TT - 1 - s) : s;
        const float* hread  = g_h[dir][(s + 1) & 1];
        float*       hwrite = g_h[dir][s & 1];

        // ---- pointwise prefetch (independent of gh) ----
        float4 pxr, pxz, pxn, php;
        {
            const float* gp = gx + ((size_t)pm * TT + t) * G3 + phc;
            pxr = __ldcs((const float4*)gp);
            pxz = __ldcs((const float4*)(gp + HH));
            pxn = __ldcs((const float4*)(gp + 2 * HH));
            php = (s > 0) ? __ldcg((const float4*)(hread + pm * HH + phc))
                          : make_float4(0.f, 0.f, 0.f, 0.f);
        }

        wmma::fragment<wmma::accumulator, 16, 16, 8, float> acc[2][3];
#pragma unroll
        for (int f = 0; f < 2; f++)
#pragma unroll
            for (int n = 0; n < 3; n++)
                wmma::fill_fragment(acc[f][n], 0.0f);

        if (s > 0) {
            const float* hrow = hread + (size_t)myrow * HH + ki * 256;
            float4 P[3][2];
            // prologue: load chunks 0,1,2; stage chunk 0
#pragma unroll
            for (int c = 0; c < 3; c++) {
                P[c][0] = __ldcg((const float4*)(hrow + c * 8));
                P[c][1] = __ldcg((const float4*)(hrow + c * 8 + 4));
            }
            {
                float* d = mybuf + lane;
                d[0*36]=P[0][0].x; d[1*36]=P[0][0].y; d[2*36]=P[0][0].z; d[3*36]=P[0][0].w;
                d[4*36]=P[0][1].x; d[5*36]=P[0][1].y; d[6*36]=P[0][1].z; d[7*36]=P[0][1].w;
            }
            __syncwarp();

#pragma unroll 4
            for (int c = 0; c < 32; c++) {
                if (c < 31) {
                    float4 s0 = P[(c + 1) % 3][0];
                    float4 s1 = P[(c + 1) % 3][1];
                    float* d = mybuf + ((c + 1) & 1) * 288 + lane;
                    d[0*36]=s0.x; d[1*36]=s0.y; d[2*36]=s0.z; d[3*36]=s0.w;
                    d[4*36]=s1.x; d[5*36]=s1.y; d[6*36]=s1.z; d[7*36]=s1.w;
                }
                if (c < 29) {
                    P[c % 3][0] = __ldcg((const float4*)(hrow + (c + 3) * 8));
                    P[c % 3][1] = __ldcg((const float4*)(hrow + (c + 3) * 8 + 4));
                }
                // mma on chunk c
                const float* bp = mybuf + (c & 1) * 288;
                const int kg = ki * 256 + c * 8;
                wmma::fragment<wmma::matrix_a, 16, 16, 8, wmma::precision::tf32,
                               wmma::col_major> af[2];
#pragma unroll
                for (int f = 0; f < 2; f++)
                    wmma::load_matrix_sync(af[f], bp + f * 16, 36);
#pragma unroll
                for (int n = 0; n < 3; n++) {
                    wmma::fragment<wmma::matrix_b, 16, 16, 8, wmma::precision::tf32,
                                   wmma::row_major> bf;
                    wmma::load_matrix_sync(bf, Whs + (size_t)kg * 48 + n * 16, 48);
#pragma unroll
                    for (int f = 0; f < 2; f++)
                        wmma::mma_sync(acc[f][n], af[f], bf, acc[f][n]);
                }
                __syncwarp();
            }
        }
        __syncthreads();   // staging buffers free; begin reduction overlay

        // ---- 4-way k reduction in smem (overlay on XB) ----
        float* P2 = XB + mi * 1536;          // partial from ki=2 (32x48)
        float* P3 = XB + 3072 + mi * 1536;   // partial from ki=3
        if (ki >= 2) {
            float* dst = (ki == 2) ? P2 : P3;
#pragma unroll
            for (int f = 0; f < 2; f++)
#pragma unroll
                for (int n = 0; n < 3; n++)
                    wmma::store_matrix_sync(dst + f * 768 + n * 16, acc[f][n],
                                            48, wmma::mem_row_major);
        }
        __syncthreads();
        if (ki < 2) {
            const float* srcp = (ki == 0) ? P2 : P3;
#pragma unroll
            for (int f = 0; f < 2; f++)
#pragma unroll
                for (int n = 0; n < 3; n++) {
                    wmma::fragment<wmma::accumulator, 16, 16, 8, float> tmp;
                    wmma::load_matrix_sync(tmp, srcp + f * 768 + n * 16, 48,
                                           wmma::mem_row_major);
#pragma unroll
                    for (int e = 0; e < tmp.num_elements; e++)
                        acc[f][n].x[e] += tmp.x[e];
                }
        }
        __syncthreads();
        if (ki == 1) {
#pragma unroll
            for (int f = 0; f < 2; f++)
#pragma unroll
                for (int n = 0; n < 3; n++)
                    wmma::store_matrix_sync(P2 + f * 768 + n * 16, acc[f][n],
                                            48, wmma::mem_row_major);
        }
        __syncthreads();
        if (ki == 0) {
#pragma unroll
            for (int f = 0; f < 2; f++)
#pragma unroll
                for (int n = 0; n < 3; n++) {
                    wmma::fragment<wmma::accumulator, 16, 16, 8, float> tmp;
                    wmma::load_matrix_sync(tmp, P2 + f * 768 + n * 16, 48,
                                           wmma::mem_row_major);
#pragma unroll
                    for (int e = 0; e < tmp.num_elements; e++)
                        acc[f][n].x[e] += tmp.x[e];
                    // final Gs at XB[(mi*32+f*16)*48 + n*16] == P2 + f*768 + n*16
                    wmma::store_matrix_sync(P2 + f * 768 + n * 16, acc[f][n],
                                            48, wmma::mem_row_major);
                }
        }
        __syncthreads();

        // ---- pointwise GRU update: thread -> (pm, 4 cols at pj) ----
        {
            float hv[4];
            const float* Gr = XB + pm * 48;
#pragma unroll
            for (int q = 0; q < 4; q++) {
                float gr = Gr[pj + q];
                float gz = Gr[16 + pj + q];
                float gn = Gr[32 + pj + q];
                float xr = ((const float*)&pxr)[q];
                float xz = ((const float*)&pxz)[q];
                float xn = ((const float*)&pxn)[q];
                float hp = ((const float*)&php)[q];
                float r = 1.f / (1.f + __expf(-(xr + br[q] + gr)));
                float z = 1.f / (1.f + __expf(-(xz + bz[q] + gz)));
                float n = tanhf(xn + bxn_[q] + r * (gn + bhn_[q]));
                hv[q] = (1.f - z) * n + z * hp;
            }
            float4 yo = make_float4(hv[0], hv[1], hv[2], hv[3]);
            *(float4*)(y + ((size_t)pm * TT + t) * HH + phc) = yo;
            float4 ho = make_float4(wmma::__float_to_tf32(hv[0]),
                                    wmma::__float_to_tf32(hv[1]),
                                    wmma::__float_to_tf32(hv[2]),
                                    wmma::__float_to_tf32(hv[3]));
            __stcg((float4*)(hwrite + pm * HH + phc), ho);
        }

        grid_barrier((unsigned)(s + 1));
    }
}

// ---------------------------------------------------------------------------
// FC bias prefill + final-hidden extraction
// ---------------------------------------------------------------------------
__global__ void fill_bias(float* __restrict__ out, const float* __restrict__ b)
{
    size_t i = (size_t)blockIdx.x * blockDim.x + threadIdx.x;
    if (i < (size_t)BT * OO) out[i] = b[i & (OO - 1)];
}

__global__ void write_finals(float* __restrict__ out)
{
    int i = blockIdx.x * blockDim.x + threadIdx.x;  // 0 .. 2*L*B*H-1
    int j = i & (HH - 1);
    int b = (i >> 10) & (BB - 1);
    int l = (i >> 16) & 1;
    int d = i >> 17;                                 // 0 = fw_h, 1 = bw_h
    const float* y = (l == 0) ? g_y0[d] : g_y1[d];
    int t = d ? 0 : (TT - 1);
    out[(size_t)BT * OO + i] = y[((size_t)b * TT + t) * HH + j];
}

// ---------------------------------------------------------------------------
// Launch sequence (graph-capturable: ~12 kernel launches, no allocs)
// ---------------------------------------------------------------------------
extern "C" void kernel_launch(void* const* d_in, const int* in_sizes, int n_in,
                              void* d_out, int out_size)
{
    const float* x       = (const float*)d_in[0];
    const float* fw_Wx0  = (const float*)d_in[1];
    const float* fw_Wh0  = (const float*)d_in[2];
    const float* fw_bx0  = (const float*)d_in[3];
    const float* fw_bh0  = (const float*)d_in[4];
    const float* fw_Wx1  = (const float*)d_in[5];
    const float* fw_Wh1  = (const float*)d_in[6];
    const float* fw_bx1  = (const float*)d_in[7];
    const float* fw_bh1  = (const float*)d_in[8];
    const float* bw_Wx0  = (const float*)d_in[9];
    const float* bw_Wh0  = (const float*)d_in[10];
    const float* bw_bx0  = (const float*)d_in[11];
    const float* bw_bh0  = (const float*)d_in[12];
    const float* bw_Wx1  = (const float*)d_in[13];
    const float* bw_Wh1  = (const float*)d_in[14];
    const float* bw_bx1  = (const float*)d_in[15];
    const float* bw_bh1  = (const float*)d_in[16];
    const float* fc_W    = (const float*)d_in[17];
    const float* fc_b    = (const float*)d_in[18];
    float* out = (float*)d_out;

    cudaFuncSetAttribute(gru_layer, cudaFuncAttributeMaxDynamicSharedMemorySize,
                         SMEM_BYTES);

    void* p;
    cudaGetSymbolAddress(&p, g_gx);
    float* gx0 = (float*)p;
    float* gx1 = gx0 + (size_t)BT * G3;
    cudaGetSymbolAddress(&p, g_y0);
    float* y00 = (float*)p;
    float* y01 = y00 + (size_t)BT * HH;
    cudaGetSymbolAddress(&p, g_y1);
    float* y10 = (float*)p;
    float* y11 = y10 + (size_t)BT * HH;

    dim3 ggx(G3 / 128, BT / 128);   // (24, 256)
    dim3 gfc(OO / 128, BT / 128);   // (4, 256)

    // Layer 0 input gates
    gemm_tf32<<<ggx, 256>>>(x, fw_Wx0, gx0, BT, G3, DD, 0);
    gemm_tf32<<<ggx, 256>>>(x, bw_Wx0, gx1, BT, G3, DD, 0);

    // Layer 0 recurrence (persistent, both dirs)
    reset_bar<<<1, 1>>>();
    gru_layer<<<NBLK, 256, SMEM_BYTES>>>(fw_Wh0, bw_Wh0, fw_bx0, fw_bh0,
                                         bw_bx0, bw_bh0, y00, y01);

    // Layer 1 input gates
    gemm_tf32<<<ggx, 256>>>(y00, fw_Wx1, gx0, BT, G3, HH, 0);
    gemm_tf32<<<ggx, 256>>>(y01, bw_Wx1, gx1, BT, G3, HH, 0);

    // Layer 1 recurrence
    reset_bar<<<1, 1>>>();
    gru_layer<<<NBLK, 256, SMEM_BYTES>>>(fw_Wh1, bw_Wh1, fw_bx1, fw_bh1,
                                         bw_bx1, bw_bh1, y10, y11);

    // FC: out = [fw_y1, bw_y1] @ fc_W + fc_b  (split-K over the two halves)
    fill_bias<<<((size_t)BT * OO + 255) / 256, 256>>>(out, fc_b);
    gemm_tf32<<<gfc, 256>>>(y10, fc_W,                   out, BT, OO, HH, 1);
    gemm_tf32<<<gfc, 256>>>(y11, fc_W + (size_t)HH * OO, out, BT, OO, HH, 1);

    // Final hidden states: fw_h [L,B,H] then bw_h [L,B,H]
    write_finals<<<(2 * LL * BB * HH) / 256, 256>>>(out);
}

// round 6
// speedup vs baseline: 1.4357x; 1.2544x over previous
#include <cuda_runtime.h>
#include <mma.h>
#include <cstdint>
#include <cstddef>

using namespace nvcuda;

// Problem dims
#define BB   64
#define TT   512
#define DD   512
#define HH   1024
#define OO   512
#define LL   2
#define G3   (3 * HH)          // 3072
#define BT   (BB * TT)         // 32768

#define NBLK 128               // persistent blocks (64 per direction)

// ---------------------------------------------------------------------------
// Scratch (static device memory; allocation-free per harness rules)
// ---------------------------------------------------------------------------
__device__ float g_gx[2][(size_t)BT * G3];       // per-dir input gates [BT, 3H]
__device__ float g_y0[2][(size_t)BT * HH];       // layer-0 outputs per dir
__device__ float g_y1[2][(size_t)BT * HH];       // layer-1 outputs per dir
__device__ float g_h[2][2][BB * HH];             // compact h, [dir][parity][64][1024]
__device__ unsigned g_bar_count;
__device__ unsigned g_bar_epoch;

__global__ void reset_bar()
{
    g_bar_count = 0;
    g_bar_epoch = 0;
}

__device__ __forceinline__ float4 tf32x4(float4 v)
{
    return make_float4(wmma::__float_to_tf32(v.x), wmma::__float_to_tf32(v.y),
                       wmma::__float_to_tf32(v.z), wmma::__float_to_tf32(v.w));
}

// ---------------------------------------------------------------------------
// Generic TF32 WMMA GEMM: C[M,N] (+)= A[M,K] @ B[K,N]
// 128x128 tile, BK=16, 256 threads. Register double-buffered global loads;
// tf32 rounding applied at the smem store (no per-fragment conversion).
// ---------------------------------------------------------------------------
__global__ void __launch_bounds__(256, 2)
gemm_tf32(const float* __restrict__ A, const float* __restrict__ Bg,
          float* __restrict__ C, int M, int N, int K, int accumulate)
{
    __shared__ float As[16][132];
    __shared__ float Bs[16][132];

    const int bm   = blockIdx.y * 128;
    const int bn   = blockIdx.x * 128;
    const int tid  = threadIdx.x;
    const int warp = tid >> 5;
    const int wm   = (warp & 3) * 32;
    const int wn   = (warp >> 2) * 64;

    wmma::fragment<wmma::accumulator, 16, 16, 8, float> acc[2][4];
#pragma unroll
    for (int i = 0; i < 2; i++)
#pragma unroll
        for (int j = 0; j < 4; j++)
            wmma::fill_fragment(acc[i][j], 0.0f);

    const int lm  = tid & 127;
    const int lkh = (tid >> 7) * 8;
    const int bk0 = (tid + 0 * 256) >> 5, bn0 = ((tid + 0 * 256) & 31) * 4;
    const int bk1 = (tid + 1 * 256) >> 5, bn1 = ((tid + 1 * 256) & 31) * 4;

    // preload k0 = 0
    const float* ap0 = A + (size_t)(bm + lm) * K + lkh;
    float4 ra0 = *(const float4*)(ap0);
    float4 ra1 = *(const float4*)(ap0 + 4);
    float4 rb0 = *(const float4*)(Bg + (size_t)bk0 * N + bn + bn0);
    float4 rb1 = *(const float4*)(Bg + (size_t)bk1 * N + bn + bn1);

    for (int k0 = 0; k0 < K; k0 += 16) {
        // stage (tf32-rounded)
        float4 a0 = tf32x4(ra0), a1 = tf32x4(ra1);
        As[lkh + 0][lm] = a0.x; As[lkh + 1][lm] = a0.y;
        As[lkh + 2][lm] = a0.z; As[lkh + 3][lm] = a0.w;
        As[lkh + 4][lm] = a1.x; As[lkh + 5][lm] = a1.y;
        As[lkh + 6][lm] = a1.z; As[lkh + 7][lm] = a1.w;
        *(float4*)&Bs[bk0][bn0] = tf32x4(rb0);
        *(float4*)&Bs[bk1][bn1] = tf32x4(rb1);
        __syncthreads();

        // prefetch next k tile into registers (hidden under the mma work)
        if (k0 + 16 < K) {
            const float* apn = ap0 + k0 + 16;
            ra0 = *(const float4*)(apn);
            ra1 = *(const float4*)(apn + 4);
            rb0 = *(const float4*)(Bg + (size_t)(k0 + 16 + bk0) * N + bn + bn0);
            rb1 = *(const float4*)(Bg + (size_t)(k0 + 16 + bk1) * N + bn + bn1);
        }

#pragma unroll
        for (int kk = 0; kk < 16; kk += 8) {
            wmma::fragment<wmma::matrix_a, 16, 16, 8, wmma::precision::tf32,
                           wmma::col_major> af[2];
#pragma unroll
            for (int i = 0; i < 2; i++)
                wmma::load_matrix_sync(af[i], &As[kk][wm + i * 16], 132);
#pragma unroll
            for (int j = 0; j < 4; j++) {
                wmma::fragment<wmma::matrix_b, 16, 16, 8, wmma::precision::tf32,
                               wmma::row_major> bf;
                wmma::load_matrix_sync(bf, &Bs[kk][wn + j * 16], 132);
#pragma unroll
                for (int i = 0; i < 2; i++)
                    wmma::mma_sync(acc[i][j], af[i], bf, acc[i][j]);
            }
        }
        __syncthreads();
    }

#pragma unroll
    for (int i = 0; i < 2; i++)
#pragma unroll
        for (int j = 0; j < 4; j++) {
            float* cp = C + (size_t)(bm + wm + i * 16) * N + bn + wn + j * 16;
            if (accumulate) {
                wmma::fragment<wmma::accumulator, 16, 16, 8, float> cf;
                wmma::load_matrix_sync(cf, cp, N, wmma::mem_row_major);
#pragma unroll
                for (int e = 0; e < cf.num_elements; e++)
                    acc[i][j].x[e] += cf.x[e];
            }
            wmma::store_matrix_sync(cp, acc[i][j], N, wmma::mem_row_major);
        }
}

// ---------------------------------------------------------------------------
// Persistent GRU layer kernel v3.
// 128 blocks (64/dir), 256 threads (8 warps = k4 x m2), 1 block/SM.
// Wh slice [1024,48] tf32 resident in SMEM. Fully-unrolled 32-chunk mma loop
// with distance-3 register prefetch (constant indices -> no local spill).
// Pairwise k-pre-reduction into 2 smem regions, scalar final sum in pointwise.
// ---------------------------------------------------------------------------
#define WHS_F   (HH * 48)            // 49152 floats (196608 B)
#define OVL_F   6144                 // overlay: staging (4608) / 2 partials (6144)
#define SMEM_BYTES ((WHS_F + OVL_F) * 4)   // 221184 B

__device__ __forceinline__ void grid_barrier(unsigned e)
{
    __syncthreads();
    if (threadIdx.x == 0) {
        __threadfence();
        unsigned arr = atomicAdd(&g_bar_count, 1u);
        if (arr == e * NBLK - 1u) {
            atomicExch(&g_bar_epoch, e);
        } else {
            while (*(volatile unsigned*)&g_bar_epoch < e) __nanosleep(32);
        }
        __threadfence();
    }
    __syncthreads();
}

__global__ void __launch_bounds__(256, 1)
gru_layer(const float* __restrict__ Wh_fw, const float* __restrict__ Wh_bw,
          const float* __restrict__ bx_fw, const float* __restrict__ bh_fw,
          const float* __restrict__ bx_bw, const float* __restrict__ bh_bw,
          float* __restrict__ y_fw, float* __restrict__ y_bw)
{
    extern __shared__ float smem[];
    float* Whs = smem;             // [1024][48] tf32
    float* XB  = smem + WHS_F;     // overlay: staging / partial regions

    const int bid = blockIdx.x;
    const int dir = bid >> 6;          // 0 = fw, 1 = bw
    const int c0  = (bid & 63) * 16;   // h-column base

    const float* Wh = dir ? Wh_bw : Wh_fw;
    const float* bx = dir ? bx_bw : bx_fw;
    const float* bh = dir ? bh_bw : bh_fw;
    float*       y  = dir ? y_bw  : y_fw;
    const float* gx = g_gx[dir];

    const int tid  = threadIdx.x;
    const int warp = tid >> 5;
    const int lane = tid & 31;
    const int ki   = warp >> 1;        // k quarter (256)
    const int mi   = warp & 1;         // m half (32 rows)

    float* mybuf = XB + warp * 576;    // 2 x [8k][36] private staging

    // ---- stage Wh slice into SMEM, tf32-rounded (once) ----
    for (int i = tid; i < WHS_F; i += 256) {
        int k = i / 48;
        int col = i - k * 48;
        int g = col >> 4;
        int j = col & 15;
        Whs[i] = wmma::__float_to_tf32(Wh[(size_t)k * G3 + g * HH + c0 + j]);
    }

    // ---- per-thread pointwise constants ----
    const int pm  = tid >> 2;          // batch row (0..63)
    const int pj  = (tid & 3) * 4;     // 4 consecutive cols
    const int phc = c0 + pj;
    float br[4], bz[4], bxn_[4], bhn_[4];
#pragma unroll
    for (int q = 0; q < 4; q++) {
        int hc = phc + q;
        br[q]   = bx[hc] + bh[hc];
        bz[q]   = bx[HH + hc] + bh[HH + hc];
        bxn_[q] = bx[2 * HH + hc];
        bhn_[q] = bh[2 * HH + hc];
    }
    __syncthreads();

    const int myrow = mi * 32 + lane;  // staged h row for this lane

    for (int s = 0; s < TT; s++) {
        const int t = dir ? (TT - 1 - s) : s;
        const float* hread  = g_h[dir][(s + 1) & 1];
        float*       hwrite = g_h[dir][s & 1];

        // ---- pointwise prefetch (independent of gh) ----
        float4 pxr, pxz, pxn, php;
        {
            const float* gp = gx + ((size_t)pm * TT + t) * G3 + phc;
            pxr = __ldcs((const float4*)gp);
            pxz = __ldcs((const float4*)(gp + HH));
            pxn = __ldcs((const float4*)(gp + 2 * HH));
            php = (s > 0) ? __ldcg((const float4*)(hread + pm * HH + phc))
                          : make_float4(0.f, 0.f, 0.f, 0.f);
        }

        wmma::fragment<wmma::accumulator, 16, 16, 8, float> acc[2][3];
#pragma unroll
        for (int f = 0; f < 2; f++)
#pragma unroll
            for (int n = 0; n < 3; n++)
                wmma::fill_fragment(acc[f][n], 0.0f);

        if (s > 0) {
            const float* hrow = hread + (size_t)myrow * HH + ki * 256;
            float4 P[3][2];
            // prologue: load chunks 0,1,2; stage chunk 0
#pragma unroll
            for (int c = 0; c < 3; c++) {
                P[c][0] = __ldcg((const float4*)(hrow + c * 8));
                P[c][1] = __ldcg((const float4*)(hrow + c * 8 + 4));
            }
            {
                float* d = mybuf + lane;
                d[0*36]=P[0][0].x; d[1*36]=P[0][0].y; d[2*36]=P[0][0].z; d[3*36]=P[0][0].w;
                d[4*36]=P[0][1].x; d[5*36]=P[0][1].y; d[6*36]=P[0][1].z; d[7*36]=P[0][1].w;
            }
            __syncwarp();

            // FULL unroll: all P indices compile-time -> P stays in registers
#pragma unroll
            for (int c = 0; c < 32; c++) {
                if (c < 31) {
                    float4 s0 = P[(c + 1) % 3][0];
                    float4 s1 = P[(c + 1) % 3][1];
                    float* d = mybuf + ((c + 1) & 1) * 288 + lane;
                    d[0*36]=s0.x; d[1*36]=s0.y; d[2*36]=s0.z; d[3*36]=s0.w;
                    d[4*36]=s1.x; d[5*36]=s1.y; d[6*36]=s1.z; d[7*36]=s1.w;
                }
                if (c < 29) {
                    P[c % 3][0] = __ldcg((const float4*)(hrow + (c + 3) * 8));
                    P[c % 3][1] = __ldcg((const float4*)(hrow + (c + 3) * 8 + 4));
                }
                const float* bp = mybuf + (c & 1) * 288;
                const int kg = ki * 256 + c * 8;
                wmma::fragment<wmma::matrix_a, 16, 16, 8, wmma::precision::tf32,
                               wmma::col_major> af[2];
#pragma unroll
                for (int f = 0; f < 2; f++)
                    wmma::load_matrix_sync(af[f], bp + f * 16, 36);
#pragma unroll
                for (int n = 0; n < 3; n++) {
                    wmma::fragment<wmma::matrix_b, 16, 16, 8, wmma::precision::tf32,
                                   wmma::row_major> bf;
                    wmma::load_matrix_sync(bf, Whs + (size_t)kg * 48 + n * 16, 48);
#pragma unroll
                    for (int f = 0; f < 2; f++)
                        wmma::mma_sync(acc[f][n], af[f], bf, acc[f][n]);
                }
                __syncwarp();
            }
        }
        __syncthreads();   // staging done; overlay becomes partial regions

        // ---- pairwise k pre-reduction into 2 regions ----
        // R[p] = XB + p*3072, holds 64x48 partial (stride 48)
        if (ki >= 2) {
            float* dst = XB + (ki - 2) * 3072;
#pragma unroll
            for (int f = 0; f < 2; f++)
#pragma unroll
                for (int n = 0; n < 3; n++)
                    wmma::store_matrix_sync(dst + (mi * 32 + f * 16) * 48 + n * 16,
                                            acc[f][n], 48, wmma::mem_row_major);
        }
        __syncthreads();
        if (ki < 2) {
            float* dst = XB + ki * 3072;
#pragma unroll
            for (int f = 0; f < 2; f++)
#pragma unroll
                for (int n = 0; n < 3; n++) {
                    float* p = dst + (mi * 32 + f * 16) * 48 + n * 16;
                    wmma::fragment<wmma::accumulator, 16, 16, 8, float> tmp;
                    wmma::load_matrix_sync(tmp, p, 48, wmma::mem_row_major);
#pragma unroll
                    for (int e = 0; e < tmp.num_elements; e++)
                        acc[f][n].x[e] += tmp.x[e];
                    wmma::store_matrix_sync(p, acc[f][n], 48, wmma::mem_row_major);
                }
        }
        __syncthreads();

        // ---- pointwise GRU update: thread -> (pm, 4 cols at pj) ----
        {
            const float* Gr = XB + pm * 48 + pj;
            float4 gr0 = *(const float4*)(Gr);
            float4 gr1 = *(const float4*)(Gr + 3072);
            float4 gz0 = *(const float4*)(Gr + 16);
            float4 gz1 = *(const float4*)(Gr + 16 + 3072);
            float4 gn0 = *(const float4*)(Gr + 32);
            float4 gn1 = *(const float4*)(Gr + 32 + 3072);

            float hv[4];
#pragma unroll
            for (int q = 0; q < 4; q++) {
                float gr = ((const float*)&gr0)[q] + ((const float*)&gr1)[q];
                float gz = ((const float*)&gz0)[q] + ((const float*)&gz1)[q];
                float gn = ((const float*)&gn0)[q] + ((const float*)&gn1)[q];
                float xr = ((const float*)&pxr)[q];
                float xz = ((const float*)&pxz)[q];
                float xn = ((const float*)&pxn)[q];
                float hp = ((const float*)&php)[q];
                float r = 1.f / (1.f + __expf(-(xr + br[q] + gr)));
                float z = 1.f / (1.f + __expf(-(xz + bz[q] + gz)));
                float n = tanhf(xn + bxn_[q] + r * (gn + bhn_[q]));
                hv[q] = (1.f - z) * n + z * hp;
            }
            *(float4*)(y + ((size_t)pm * TT + t) * HH + phc) =
                make_float4(hv[0], hv[1], hv[2], hv[3]);
            __stcg((float4*)(hwrite + pm * HH + phc),
                   make_float4(wmma::__float_to_tf32(hv[0]),
                               wmma::__float_to_tf32(hv[1]),
                               wmma::__float_to_tf32(hv[2]),
                               wmma::__float_to_tf32(hv[3])));
        }

        grid_barrier((unsigned)(s + 1));
    }
}

// ---------------------------------------------------------------------------
// FC bias prefill + final-hidden extraction
// ---------------------------------------------------------------------------
__global__ void fill_bias(float* __restrict__ out, const float* __restrict__ b)
{
    size_t i = (size_t)blockIdx.x * blockDim.x + threadIdx.x;
    if (i < (size_t)BT * OO) out[i] = b[i & (OO - 1)];
}

__global__ void write_finals(float* __restrict__ out)
{
    int i = blockIdx.x * blockDim.x + threadIdx.x;  // 0 .. 2*L*B*H-1
    int j = i & (HH - 1);
    int b = (i >> 10) & (BB - 1);
    int l = (i >> 16) & 1;
    int d = i >> 17;                                 // 0 = fw_h, 1 = bw_h
    const float* y = (l == 0) ? g_y0[d] : g_y1[d];
    int t = d ? 0 : (TT - 1);
    out[(size_t)BT * OO + i] = y[((size_t)b * TT + t) * HH + j];
}

// ---------------------------------------------------------------------------
// Launch sequence (graph-capturable: ~12 kernel launches, no allocs)
// ---------------------------------------------------------------------------
extern "C" void kernel_launch(void* const* d_in, const int* in_sizes, int n_in,
                              void* d_out, int out_size)
{
    const float* x       = (const float*)d_in[0];
    const float* fw_Wx0  = (const float*)d_in[1];
    const float* fw_Wh0  = (const float*)d_in[2];
    const float* fw_bx0  = (const float*)d_in[3];
    const float* fw_bh0  = (const float*)d_in[4];
    const float* fw_Wx1  = (const float*)d_in[5];
    const float* fw_Wh1  = (const float*)d_in[6];
    const float* fw_bx1  = (const float*)d_in[7];
    const float* fw_bh1  = (const float*)d_in[8];
    const float* bw_Wx0  = (const float*)d_in[9];
    const float* bw_Wh0  = (const float*)d_in[10];
    const float* bw_bx0  = (const float*)d_in[11];
    const float* bw_bh0  = (const float*)d_in[12];
    const float* bw_Wx1  = (const float*)d_in[13];
    const float* bw_Wh1  = (const float*)d_in[14];
    const float* bw_bx1  = (const float*)d_in[15];
    const float* bw_bh1  = (const float*)d_in[16];
    const float* fc_W    = (const float*)d_in[17];
    const float* fc_b    = (const float*)d_in[18];
    float* out = (float*)d_out;

    cudaFuncSetAttribute(gru_layer, cudaFuncAttributeMaxDynamicSharedMemorySize,
                         SMEM_BYTES);

    void* p;
    cudaGetSymbolAddress(&p, g_gx);
    float* gx0 = (float*)p;
    float* gx1 = gx0 + (size_t)BT * G3;
    cudaGetSymbolAddress(&p, g_y0);
    float* y00 = (float*)p;
    float* y01 = y00 + (size_t)BT * HH;
    cudaGetSymbolAddress(&p, g_y1);
    float* y10 = (float*)p;
    float* y11 = y10 + (size_t)BT * HH;

    dim3 ggx(G3 / 128, BT / 128);   // (24, 256)
    dim3 gfc(OO / 128, BT / 128);   // (4, 256)

    // Layer 0 input gates
    gemm_tf32<<<ggx, 256>>>(x, fw_Wx0, gx0, BT, G3, DD, 0);
    gemm_tf32<<<ggx, 256>>>(x, bw_Wx0, gx1, BT, G3, DD, 0);

    // Layer 0 recurrence (persistent, both dirs)
    reset_bar<<<1, 1>>>();
    gru_layer<<<NBLK, 256, SMEM_BYTES>>>(fw_Wh0, bw_Wh0, fw_bx0, fw_bh0,
                                         bw_bx0, bw_bh0, y00, y01);

    // Layer 1 input gates
    gemm_tf32<<<ggx, 256>>>(y00, fw_Wx1, gx0, BT, G3, HH, 0);
    gemm_tf32<<<ggx, 256>>>(y01, bw_Wx1, gx1, BT, G3, HH, 0);

    // Layer 1 recurrence
    reset_bar<<<1, 1>>>();
    gru_layer<<<NBLK, 256, SMEM_BYTES>>>(fw_Wh1, bw_Wh1, fw_bx1, fw_bh1,
                                         bw_bx1, bw_bh1, y10, y11);

    // FC: out = [fw_y1, bw_y1] @ fc_W + fc_b  (split-K over the two halves)
    fill_bias<<<((size_t)BT * OO + 255) / 256, 256>>>(out, fc_b);
    gemm_tf32<<<gfc, 256>>>(y10, fc_W,                   out, BT, OO, HH, 1);
    gemm_tf32<<<gfc, 256>>>(y11, fc_W + (size_t)HH * OO, out, BT, OO, HH, 1);

    // Final hidden states: fw_h [L,B,H] then bw_h [L,B,H]
    write_finals<<<(2 * LL * BB * HH) / 256, 256>>>(out);
}